// round 15
// baseline (speedup 1.0000x reference)
#include <cuda_runtime.h>
#include <math.h>

// 64 graphs x 2048 nodes x 128 dim, 128 perspectives. Output (131072,128) f32.
// att_p = p (h^T h): Gram restructuring, O(L*D^2) per graph.
#define G_TOTAL 64
#define L_ROWS  2048
#define D_DIM   128
#define P_DIM   128
#define CHUNKS  16
#define CHUNK_ROWS (L_ROWS / CHUNKS)   // 128
#define TRM     64                      // rows per match-kernel block (4 rows/thread)
#define PT      132                     // shared pitch: 528B rows, 16B-aligned, LDS.128 conflict-free

typedef unsigned long long u64pk;       // packed f32x2

__device__ __forceinline__ u64pk f2fma(u64pk a, u64pk b, u64pk c) {
    u64pk d;
    asm("fma.rn.f32x2 %0, %1, %2, %3;" : "=l"(d) : "l"(a), "l"(b), "l"(c));
    return d;
}
__device__ __forceinline__ u64pk f2mul(u64pk a, u64pk b) {
    u64pk d;
    asm("mul.rn.f32x2 %0, %1, %2;" : "=l"(d) : "l"(a), "l"(b));
    return d;
}
__device__ __forceinline__ u64pk f2bcast(float a) {   // {a, a}
    u64pk d;
    asm("mov.b64 %0, {%1, %1};" : "=l"(d) : "f"(a));
    return d;
}
__device__ __forceinline__ float f2sum(u64pk a) {
    float lo, hi;
    asm("mov.b64 {%0, %1}, %2;" : "=f"(lo), "=f"(hi) : "l"(a));
    return lo + hi;
}

__device__ float g_gram_part[(size_t)CHUNKS * G_TOTAL * D_DIM * D_DIM]; // 64 MB
__device__ float g_gram[(size_t)G_TOTAL * D_DIM * D_DIM];               //  4 MB

// ---------------------------------------------------------------------------
// Kernel 1: partial Gram, f32x2-packed, DOUBLE-BUFFERED staging.
// Ping-pong: issue LDG for tile t+1, compute tile t, STS t+1, one sync/iter.
// Hides the ~400-600cyc DRAM latency that capped fma at 61.6%.
// ---------------------------------------------------------------------------
__global__ __launch_bounds__(256, 2) void gram_partial_kernel(const float* __restrict__ feats) {
    const int chunk = blockIdx.x & (CHUNKS - 1);
    const int graph = blockIdx.x >> 4;

    __shared__ float sA[2][16 * D_DIM];   // 2 x 8KB ping-pong

    const int tid = threadIdx.x;
    const int tx = tid & 15;
    const int ty = tid >> 4;

    u64pk acc[8][2][2];
#pragma unroll
    for (int i = 0; i < 8; i++)
#pragma unroll
        for (int j = 0; j < 2; j++) { acc[i][j][0] = 0ull; acc[i][j][1] = 0ull; }

    const float4* src = (const float4*)(feats +
        ((size_t)graph * L_ROWS + (size_t)chunk * CHUNK_ROWS) * D_DIM);

    // Prologue: stage tile 0 into buffer 0.
    {
        float4 c0 = src[tid], c1 = src[tid + 256];
        ((float4*)sA[0])[tid] = c0;
        ((float4*)sA[0])[tid + 256] = c1;
    }
    __syncthreads();

    const int NT = CHUNK_ROWS / 16;   // 8 tiles
#pragma unroll 1
    for (int t = 0; t < NT; t++) {
        float4 n0, n1;
        if (t + 1 < NT) {                       // issue next tile's LDG early
            n0 = src[(t + 1) * 512 + tid];
            n1 = src[(t + 1) * 512 + tid + 256];
        }
        const float* buf = sA[t & 1];
#pragma unroll
        for (int k = 0; k < 16; k++) {
            ulonglong2 bq[2];
            bq[0] = *(const ulonglong2*)&buf[k * D_DIM + 4 * tx];
            bq[1] = *(const ulonglong2*)&buf[k * D_DIM + 4 * tx + 64];
            float4 av0 = *(const float4*)&buf[k * D_DIM + 8 * ty];
            float4 av1 = *(const float4*)&buf[k * D_DIM + 8 * ty + 4];
            u64pk a[8];
            a[0] = f2bcast(av0.x); a[1] = f2bcast(av0.y);
            a[2] = f2bcast(av0.z); a[3] = f2bcast(av0.w);
            a[4] = f2bcast(av1.x); a[5] = f2bcast(av1.y);
            a[6] = f2bcast(av1.z); a[7] = f2bcast(av1.w);
#pragma unroll
            for (int i = 0; i < 8; i++)
#pragma unroll
                for (int j = 0; j < 2; j++) {
                    acc[i][j][0] = f2fma(a[i], bq[j].x, acc[i][j][0]);
                    acc[i][j][1] = f2fma(a[i], bq[j].y, acc[i][j][1]);
                }
        }
        if (t + 1 < NT) {                       // LDG landed during compute
            float4* db = (float4*)sA[(t + 1) & 1];
            db[tid] = n0;
            db[tid + 256] = n1;
        }
        __syncthreads();
    }

    float* outp = g_gram_part + ((size_t)chunk * G_TOTAL + graph) * (size_t)(D_DIM * D_DIM);
#pragma unroll
    for (int i = 0; i < 8; i++)
#pragma unroll
        for (int j = 0; j < 2; j++) {
            ulonglong2 v; v.x = acc[i][j][0]; v.y = acc[i][j][1];
            *(ulonglong2*)&outp[(8 * ty + i) * D_DIM + 4 * tx + 64 * j] = v;
        }
}

// ---------------------------------------------------------------------------
// Kernel 2: reduce partials. HBM-bound, float4, 16 independent streams.
// ---------------------------------------------------------------------------
__global__ __launch_bounds__(256) void gram_reduce_kernel() {
    const size_t v = (size_t)blockIdx.x * 256 + threadIdx.x;
    const float4* src = (const float4*)g_gram_part;
    const size_t stride4 = (size_t)(G_TOTAL * D_DIM * D_DIM) / 4;
    float4 s = src[v];
#pragma unroll
    for (int c = 1; c < CHUNKS; c++) {
        float4 t = src[(size_t)c * stride4 + v];
        s.x += t.x; s.y += t.y; s.z += t.z; s.w += t.w;
    }
    ((float4*)g_gram)[v] = s;
}

// ---------------------------------------------------------------------------
// Kernel 3: fused match. 256 threads, TRM=64 rows/block, 1 block/SM (135KB smem).
//   Phase B: 4 rows/thread -> Gram smem traffic per FFMA2 halved (smem 136 cyc
//            vs fma 256 cyc per k4 SM-wide: cleanly fma-bound).
//   Phase D: 4 passes x 1 row (same per-pass body as the validated version).
// ---------------------------------------------------------------------------
__global__ __launch_bounds__(256, 1) void match_kernel(const float* __restrict__ feats,
                                                       const float* __restrict__ mp_w,
                                                       float* __restrict__ out) {
    extern __shared__ float smem[];
    float* sM  = smem;                     // 128 * PT  (Gram, then w2 [pp][k])
    float* sV1 = sM + D_DIM * PT;          // TRM * PT
    float* sV2 = sV1 + TRM * PT;           // TRM * PT

    const int graph = blockIdx.x >> 5;     // 32 tiles per graph (2048/64)
    const int tile  = blockIdx.x & 31;
    const int partner = graph ^ 1;
    const int tid = threadIdx.x;
    const int tx = tid & 15;
    const int ty = tid >> 4;

    // Stage partner Gram via float4.
    const float4* Mg4 = (const float4*)(g_gram + (size_t)partner * (D_DIM * D_DIM));
    for (int i4 = tid; i4 < (D_DIM * D_DIM) / 4; i4 += 256) {
        float4 v = Mg4[i4];
        *(float4*)&sM[(i4 >> 5) * PT + (i4 & 31) * 4] = v;
    }

    // Stage V1 tile (TRM x 128) via float4.
    const float4* vb = (const float4*)(feats + ((size_t)graph * L_ROWS + (size_t)tile * TRM) * D_DIM);
    for (int i = tid; i < TRM * (D_DIM / 4); i += 256) {
        float4 v = vb[i];
        *(float4*)&sV1[(i >> 5) * PT + (i & 31) * 4] = v;
    }
    __syncthreads();

    // ---- Phase B: V2 = V1 @ M, 4 rows/thread, packed k-pairs ----
    {
        u64pk acc[4][8];
#pragma unroll
        for (int ri = 0; ri < 4; ri++)
#pragma unroll
            for (int ci = 0; ci < 8; ci++) acc[ri][ci] = 0ull;

#pragma unroll 2
        for (int k4 = 0; k4 < D_DIM / 4; k4++) {
            ulonglong2 va[4];
#pragma unroll
            for (int ri = 0; ri < 4; ri++)
                va[ri] = *(const ulonglong2*)&sV1[(ty + 16 * ri) * PT + 4 * k4];
#pragma unroll
            for (int ci = 0; ci < 8; ci++) {
                ulonglong2 bq = *(const ulonglong2*)&sM[(tx + 16 * ci) * PT + 4 * k4];
#pragma unroll
                for (int ri = 0; ri < 4; ri++) {
                    acc[ri][ci] = f2fma(va[ri].x, bq.x, acc[ri][ci]);
                    acc[ri][ci] = f2fma(va[ri].y, bq.y, acc[ri][ci]);
                }
            }
        }
#pragma unroll
        for (int ri = 0; ri < 4; ri++)
#pragma unroll
            for (int ci = 0; ci < 8; ci++)
                sV2[(ty + 16 * ri) * PT + tx + 16 * ci] = f2sum(acc[ri][ci]);
    }
    __syncthreads();

    // ---- Phase C: sM <- w^2, [pp][k], float4 ----
    const float4* w4 = (const float4*)mp_w;
    for (int i4 = tid; i4 < (P_DIM * D_DIM) / 4; i4 += 256) {
        float4 w = w4[i4];
        w.x *= w.x; w.y *= w.y; w.z *= w.z; w.w *= w.w;
        *(float4*)&sM[(i4 >> 5) * PT + (i4 & 31) * 4] = w;
    }
    __syncthreads();

    // ---- Phase D: packed num/n1/n2 reductions, 4 row passes ----
    const size_t rowbase = (size_t)graph * L_ROWS + (size_t)tile * TRM;
#pragma unroll 1
    for (int pass = 0; pass < 4; pass++) {
        const int row = ty + 16 * pass;
        u64pk an[8], a1[8], a2[8];
#pragma unroll
        for (int ci = 0; ci < 8; ci++) { an[ci] = 0ull; a1[ci] = 0ull; a2[ci] = 0ull; }

#pragma unroll 2
        for (int k4 = 0; k4 < D_DIM / 4; k4++) {
            ulonglong2 x = *(const ulonglong2*)&sV1[row * PT + 4 * k4];
            ulonglong2 y = *(const ulonglong2*)&sV2[row * PT + 4 * k4];

            u64pk u0  = f2mul(x.x, y.x), u1  = f2mul(x.y, y.y);
            u64pk s10 = f2mul(x.x, x.x), s11 = f2mul(x.y, x.y);
            u64pk s20 = f2mul(y.x, y.x), s21 = f2mul(y.y, y.y);

#pragma unroll
            for (int ci = 0; ci < 8; ci++) {
                ulonglong2 wq = *(const ulonglong2*)&sM[(tx + 16 * ci) * PT + 4 * k4];
                an[ci] = f2fma(u0,  wq.x, an[ci]);
                an[ci] = f2fma(u1,  wq.y, an[ci]);
                a1[ci] = f2fma(s10, wq.x, a1[ci]);
                a1[ci] = f2fma(s11, wq.y, a1[ci]);
                a2[ci] = f2fma(s20, wq.x, a2[ci]);
                a2[ci] = f2fma(s21, wq.y, a2[ci]);
            }
        }

        float* orow = &out[(rowbase + row) * (size_t)P_DIM];
#pragma unroll
        for (int ci = 0; ci < 8; ci++) {
            const float num = f2sum(an[ci]);
            const float n1  = f2sum(a1[ci]);
            const float n2  = f2sum(a2[ci]);
            const float denom = fmaxf(sqrtf(n1) * sqrtf(n2), 1e-8f);
            orow[tx + 16 * ci] = num / denom;
        }
    }
}

// ---------------------------------------------------------------------------
extern "C" void kernel_launch(void* const* d_in, const int* in_sizes, int n_in,
                              void* d_out, int out_size) {
    (void)in_sizes; (void)n_in; (void)out_size;
    const float* feats = (const float*)d_in[0];   // (131072, 128) f32
    const float* mp_w  = (const float*)d_in[1];   // (128, 128) f32
    float* out = (float*)d_out;                   // (131072, 128) f32

    const size_t smem_bytes = (size_t)((D_DIM + 2 * TRM) * PT) * sizeof(float); // 135,168 B
    cudaFuncSetAttribute(match_kernel, cudaFuncAttributeMaxDynamicSharedMemorySize, (int)smem_bytes);

    gram_partial_kernel<<<CHUNKS * G_TOTAL, 256>>>(feats);
    gram_reduce_kernel<<<(G_TOTAL * D_DIM * D_DIM) / (256 * 4), 256>>>();
    match_kernel<<<G_TOTAL * (L_ROWS / TRM), 256, smem_bytes>>>(feats, mp_w, out);
}

// round 16
// speedup vs baseline: 1.1670x; 1.1670x over previous
#include <cuda_runtime.h>
#include <math.h>

// 64 graphs x 2048 nodes x 128 dim, 128 perspectives. Output (131072,128) f32.
// att_p = p (h^T h): Gram restructuring, O(L*D^2) per graph.
#define G_TOTAL 64
#define L_ROWS  2048
#define D_DIM   128
#define P_DIM   128
#define CHUNKS  16
#define CHUNK_ROWS (L_ROWS / CHUNKS)   // 128
#define TR      32                      // rows per match-kernel block (validated: 2 blocks/SM)
#define PT      132                     // shared pitch: 528B rows, 16B-aligned, LDS.128 conflict-free

typedef unsigned long long u64pk;       // packed f32x2

__device__ __forceinline__ u64pk f2fma(u64pk a, u64pk b, u64pk c) {
    u64pk d;
    asm("fma.rn.f32x2 %0, %1, %2, %3;" : "=l"(d) : "l"(a), "l"(b), "l"(c));
    return d;
}
__device__ __forceinline__ u64pk f2mul(u64pk a, u64pk b) {
    u64pk d;
    asm("mul.rn.f32x2 %0, %1, %2;" : "=l"(d) : "l"(a), "l"(b));
    return d;
}
__device__ __forceinline__ u64pk f2bcast(float a) {   // {a, a}
    u64pk d;
    asm("mov.b64 %0, {%1, %1};" : "=l"(d) : "f"(a));
    return d;
}
__device__ __forceinline__ float f2sum(u64pk a) {
    float lo, hi;
    asm("mov.b64 {%0, %1}, %2;" : "=f"(lo), "=f"(hi) : "l"(a));
    return lo + hi;
}

__device__ float g_gram_part[(size_t)CHUNKS * G_TOTAL * D_DIM * D_DIM]; // 64 MB
__device__ float g_gram[(size_t)G_TOTAL * D_DIM * D_DIM];               //  4 MB

// ---------------------------------------------------------------------------
// Kernel 1: partial Gram, f32x2-packed, double-buffered staging.
// MEASURED: 81.5us (vs 87.2 single-buffered), fma pipe 65.9%, ~78% of the
// FFMA2-issue floor -> near structural limit for this shape. KEEP.
// ---------------------------------------------------------------------------
__global__ __launch_bounds__(256, 2) void gram_partial_kernel(const float* __restrict__ feats) {
    const int chunk = blockIdx.x & (CHUNKS - 1);
    const int graph = blockIdx.x >> 4;

    __shared__ float sA[2][16 * D_DIM];   // 2 x 8KB ping-pong

    const int tid = threadIdx.x;
    const int tx = tid & 15;
    const int ty = tid >> 4;

    u64pk acc[8][2][2];
#pragma unroll
    for (int i = 0; i < 8; i++)
#pragma unroll
        for (int j = 0; j < 2; j++) { acc[i][j][0] = 0ull; acc[i][j][1] = 0ull; }

    const float4* src = (const float4*)(feats +
        ((size_t)graph * L_ROWS + (size_t)chunk * CHUNK_ROWS) * D_DIM);

    {
        float4 c0 = src[tid], c1 = src[tid + 256];
        ((float4*)sA[0])[tid] = c0;
        ((float4*)sA[0])[tid + 256] = c1;
    }
    __syncthreads();

    const int NT = CHUNK_ROWS / 16;   // 8 tiles
#pragma unroll 1
    for (int t = 0; t < NT; t++) {
        float4 n0, n1;
        if (t + 1 < NT) {
            n0 = src[(t + 1) * 512 + tid];
            n1 = src[(t + 1) * 512 + tid + 256];
        }
        const float* buf = sA[t & 1];
#pragma unroll
        for (int k = 0; k < 16; k++) {
            ulonglong2 bq[2];
            bq[0] = *(const ulonglong2*)&buf[k * D_DIM + 4 * tx];
            bq[1] = *(const ulonglong2*)&buf[k * D_DIM + 4 * tx + 64];
            float4 av0 = *(const float4*)&buf[k * D_DIM + 8 * ty];
            float4 av1 = *(const float4*)&buf[k * D_DIM + 8 * ty + 4];
            u64pk a[8];
            a[0] = f2bcast(av0.x); a[1] = f2bcast(av0.y);
            a[2] = f2bcast(av0.z); a[3] = f2bcast(av0.w);
            a[4] = f2bcast(av1.x); a[5] = f2bcast(av1.y);
            a[6] = f2bcast(av1.z); a[7] = f2bcast(av1.w);
#pragma unroll
            for (int i = 0; i < 8; i++)
#pragma unroll
                for (int j = 0; j < 2; j++) {
                    acc[i][j][0] = f2fma(a[i], bq[j].x, acc[i][j][0]);
                    acc[i][j][1] = f2fma(a[i], bq[j].y, acc[i][j][1]);
                }
        }
        if (t + 1 < NT) {
            float4* db = (float4*)sA[(t + 1) & 1];
            db[tid] = n0;
            db[tid + 256] = n1;
        }
        __syncthreads();
    }

    float* outp = g_gram_part + ((size_t)chunk * G_TOTAL + graph) * (size_t)(D_DIM * D_DIM);
#pragma unroll
    for (int i = 0; i < 8; i++)
#pragma unroll
        for (int j = 0; j < 2; j++) {
            ulonglong2 v; v.x = acc[i][j][0]; v.y = acc[i][j][1];
            *(ulonglong2*)&outp[(8 * ty + i) * D_DIM + 4 * tx + 64 * j] = v;
        }
}

// ---------------------------------------------------------------------------
// Kernel 2: reduce partials. HBM-bound, float4, 16 independent streams.
// ---------------------------------------------------------------------------
__global__ __launch_bounds__(256) void gram_reduce_kernel() {
    const size_t v = (size_t)blockIdx.x * 256 + threadIdx.x;
    const float4* src = (const float4*)g_gram_part;
    const size_t stride4 = (size_t)(G_TOTAL * D_DIM * D_DIM) / 4;
    float4 s = src[v];
#pragma unroll
    for (int c = 1; c < CHUNKS; c++) {
        float4 t = src[(size_t)c * stride4 + v];
        s.x += t.x; s.y += t.y; s.z += t.z; s.w += t.w;
    }
    ((float4*)g_gram)[v] = s;
}

// ---------------------------------------------------------------------------
// Kernel 3: fused match — REVERTED to the measured-good TR=32 / 2-blocks-per-SM
// configuration (~490us inside the 587.3 run). The TRM=64 1-block/SM variant
// measured +100us: occupancy cover beats crossbar-traffic reduction here.
// ---------------------------------------------------------------------------
__global__ __launch_bounds__(256, 2) void match_kernel(const float* __restrict__ feats,
                                                       const float* __restrict__ mp_w,
                                                       float* __restrict__ out) {
    extern __shared__ float smem[];
    float* sM  = smem;                     // 128 * PT  (Gram, then w2 [pp][k])
    float* sV1 = sM + D_DIM * PT;          // TR * PT
    float* sV2 = sV1 + TR * PT;            // TR * PT

    const int graph = blockIdx.x >> 6;     // 64 tiles per graph (2048/32)
    const int tile  = blockIdx.x & 63;
    const int partner = graph ^ 1;
    const int tid = threadIdx.x;
    const int tx = tid & 15;
    const int ty = tid >> 4;
    const int r0 = ty, r1 = ty + 16;

    // Stage partner Gram via float4.
    const float4* Mg4 = (const float4*)(g_gram + (size_t)partner * (D_DIM * D_DIM));
    for (int i4 = tid; i4 < (D_DIM * D_DIM) / 4; i4 += 256) {
        float4 v = Mg4[i4];
        *(float4*)&sM[(i4 >> 5) * PT + (i4 & 31) * 4] = v;
    }

    // Stage V1 tile (TR x 128) via float4.
    const float4* vb = (const float4*)(feats + ((size_t)graph * L_ROWS + (size_t)tile * TR) * D_DIM);
    for (int i = tid; i < TR * (D_DIM / 4); i += 256) {
        float4 v = vb[i];
        *(float4*)&sV1[(i >> 5) * PT + (i & 31) * 4] = v;
    }
    __syncthreads();

    // ---- Phase B: V2 = V1 @ M, 2 rows/thread, packed k-pairs ----
    {
        u64pk acc[2][8];
#pragma unroll
        for (int ri = 0; ri < 2; ri++)
#pragma unroll
            for (int ci = 0; ci < 8; ci++) acc[ri][ci] = 0ull;

#pragma unroll 2
        for (int k4 = 0; k4 < D_DIM / 4; k4++) {
            ulonglong2 va0 = *(const ulonglong2*)&sV1[r0 * PT + 4 * k4];
            ulonglong2 va1 = *(const ulonglong2*)&sV1[r1 * PT + 4 * k4];
#pragma unroll
            for (int ci = 0; ci < 8; ci++) {
                ulonglong2 bq = *(const ulonglong2*)&sM[(tx + 16 * ci) * PT + 4 * k4];
                acc[0][ci] = f2fma(va0.x, bq.x, acc[0][ci]);
                acc[0][ci] = f2fma(va0.y, bq.y, acc[0][ci]);
                acc[1][ci] = f2fma(va1.x, bq.x, acc[1][ci]);
                acc[1][ci] = f2fma(va1.y, bq.y, acc[1][ci]);
            }
        }
#pragma unroll
        for (int ri = 0; ri < 2; ri++)
#pragma unroll
            for (int ci = 0; ci < 8; ci++)
                sV2[(ty + 16 * ri) * PT + tx + 16 * ci] = f2sum(acc[ri][ci]);
    }
    __syncthreads();

    // ---- Phase C: sM <- w^2, [pp][k], float4 ----
    const float4* w4 = (const float4*)mp_w;
    for (int i4 = tid; i4 < (P_DIM * D_DIM) / 4; i4 += 256) {
        float4 w = w4[i4];
        w.x *= w.x; w.y *= w.y; w.z *= w.z; w.w *= w.w;
        *(float4*)&sM[(i4 >> 5) * PT + (i4 & 31) * 4] = w;
    }
    __syncthreads();

    // ---- Phase D: packed num/n1/n2 reductions, two ROW passes ----
    const size_t rowbase = (size_t)graph * L_ROWS + (size_t)tile * TR;
#pragma unroll 1
    for (int pass = 0; pass < 2; pass++) {
        const int row = ty + 16 * pass;
        u64pk an[8], a1[8], a2[8];
#pragma unroll
        for (int ci = 0; ci < 8; ci++) { an[ci] = 0ull; a1[ci] = 0ull; a2[ci] = 0ull; }

#pragma unroll 2
        for (int k4 = 0; k4 < D_DIM / 4; k4++) {
            ulonglong2 x = *(const ulonglong2*)&sV1[row * PT + 4 * k4];
            ulonglong2 y = *(const ulonglong2*)&sV2[row * PT + 4 * k4];

            u64pk u0  = f2mul(x.x, y.x), u1  = f2mul(x.y, y.y);
            u64pk s10 = f2mul(x.x, x.x), s11 = f2mul(x.y, x.y);
            u64pk s20 = f2mul(y.x, y.x), s21 = f2mul(y.y, y.y);

#pragma unroll
            for (int ci = 0; ci < 8; ci++) {
                ulonglong2 wq = *(const ulonglong2*)&sM[(tx + 16 * ci) * PT + 4 * k4];
                an[ci] = f2fma(u0,  wq.x, an[ci]);
                an[ci] = f2fma(u1,  wq.y, an[ci]);
                a1[ci] = f2fma(s10, wq.x, a1[ci]);
                a1[ci] = f2fma(s11, wq.y, a1[ci]);
                a2[ci] = f2fma(s20, wq.x, a2[ci]);
                a2[ci] = f2fma(s21, wq.y, a2[ci]);
            }
        }

        float* orow = &out[(rowbase + row) * (size_t)P_DIM];
#pragma unroll
        for (int ci = 0; ci < 8; ci++) {
            const float num = f2sum(an[ci]);
            const float n1  = f2sum(a1[ci]);
            const float n2  = f2sum(a2[ci]);
            const float denom = fmaxf(sqrtf(n1) * sqrtf(n2), 1e-8f);
            orow[tx + 16 * ci] = num / denom;
        }
    }
}

// ---------------------------------------------------------------------------
extern "C" void kernel_launch(void* const* d_in, const int* in_sizes, int n_in,
                              void* d_out, int out_size) {
    (void)in_sizes; (void)n_in; (void)out_size;
    const float* feats = (const float*)d_in[0];   // (131072, 128) f32
    const float* mp_w  = (const float*)d_in[1];   // (128, 128) f32
    float* out = (float*)d_out;                   // (131072, 128) f32

    const size_t smem_bytes = (size_t)((D_DIM + 2 * TR) * PT) * sizeof(float); // 101,376 B
    cudaFuncSetAttribute(match_kernel, cudaFuncAttributeMaxDynamicSharedMemorySize, (int)smem_bytes);

    gram_partial_kernel<<<CHUNKS * G_TOTAL, 256>>>(feats);
    gram_reduce_kernel<<<(G_TOTAL * D_DIM * D_DIM) / (256 * 4), 256>>>();
    match_kernel<<<G_TOTAL * (L_ROWS / TR), 256, smem_bytes>>>(feats, mp_w, out);
}